// round 15
// baseline (speedup 1.0000x reference)
#include <cuda_runtime.h>
#include <cuda_bf16.h>
#include <cstdint>

#define NN 8192
#define DD 256
#define EE 131072

#define SMEM_SWIZZLE_128B(o) ((o) ^ (((o) >> 3) & 0x70))
#define SMEM_SWIZZLE_64B(o)  ((o) ^ (((o) >> 3) & 0x30))

// ---------------------------------------------------------------------------
// Scratch (static device allocations — allowed)
// ---------------------------------------------------------------------------
__device__ float g_E1[NN * DD];
__device__ float g_H[NN * DD];
__device__ float g_O1[NN * DD];
__device__ float g_P[NN * DD];
__device__ __nv_bfloat16 g_Bth[DD * NN];
__device__ __nv_bfloat16 g_Btl[DD * NN];
__device__ __nv_bfloat16 g_Wh[DD * DD];
__device__ __nv_bfloat16 g_Wl[DD * DD];
__device__ float g_rs[NN];
__device__ float g_dinv1[NN];
__device__ float g_dinv2[NN];

// ---------------------------------------------------------------------------
// PTX wrappers (sm_80/sm_90 base-target instructions only)
// ---------------------------------------------------------------------------
__device__ __forceinline__ uint32_t smem_to_u32(const void* p) {
    uint32_t a;
    asm("{ .reg .u64 t; cvta.to.shared.u64 t, %1; cvt.u32.u64 %0, t; }" : "=r"(a) : "l"(p));
    return a;
}
__device__ __forceinline__ void ldsm4(uint32_t* r, uint32_t addr) {
    asm volatile("ldmatrix.sync.aligned.m8n8.x4.shared.b16 {%0,%1,%2,%3}, [%4];"
                 : "=r"(r[0]), "=r"(r[1]), "=r"(r[2]), "=r"(r[3]) : "r"(addr));
}
__device__ __forceinline__ void mma16816(float* c, const uint32_t* a, uint32_t b0, uint32_t b1) {
    asm volatile(
        "mma.sync.aligned.m16n8k16.row.col.f32.bf16.bf16.f32 "
        "{%0,%1,%2,%3}, {%4,%5,%6,%7}, {%8,%9}, {%0,%1,%2,%3};"
        : "+f"(c[0]), "+f"(c[1]), "+f"(c[2]), "+f"(c[3])
        : "r"(a[0]), "r"(a[1]), "r"(a[2]), "r"(a[3]), "r"(b0), "r"(b1));
}
#define CP_ASYNC16(dst, src) \
    asm volatile("cp.async.cg.shared.global [%0], [%1], 16;" :: "r"(dst), "l"(src))
#define CP_COMMIT() asm volatile("cp.async.commit_group;" ::: "memory")
#define CP_WAIT0() asm volatile("cp.async.wait_group 0;" ::: "memory")
__device__ __forceinline__ void red_add_v4(float* p, float a, float b, float c, float d) {
    asm volatile("red.global.add.v4.f32 [%0], {%1, %2, %3, %4};"
                 :: "l"(p), "f"(a), "f"(b), "f"(c), "f"(d) : "memory");
}
__device__ __forceinline__ void red_add_v2(float* p, float a, float b) {
    asm volatile("red.global.add.v2.f32 [%0], {%1, %2};"
                 :: "l"(p), "f"(a), "f"(b) : "memory");
}
__device__ __forceinline__ void red_add_f32(float* p, float v) {
    asm volatile("red.global.add.f32 [%0], %1;" :: "l"(p), "f"(v) : "memory");
}

// ---------------------------------------------------------------------------
// conversions
// ---------------------------------------------------------------------------
__device__ __forceinline__ void cvt8(const float4 x, const float4 y, uint4& hi, uint4& lo) {
    __nv_bfloat162 h0 = __floats2bfloat162_rn(x.x, x.y);
    __nv_bfloat162 h1 = __floats2bfloat162_rn(x.z, x.w);
    __nv_bfloat162 h2 = __floats2bfloat162_rn(y.x, y.y);
    __nv_bfloat162 h3 = __floats2bfloat162_rn(y.z, y.w);
    hi.x = *(uint32_t*)&h0; hi.y = *(uint32_t*)&h1;
    hi.z = *(uint32_t*)&h2; hi.w = *(uint32_t*)&h3;
    float2 f0 = __bfloat1622float2(h0);
    float2 f1 = __bfloat1622float2(h1);
    float2 f2 = __bfloat1622float2(h2);
    float2 f3 = __bfloat1622float2(h3);
    __nv_bfloat162 l0 = __floats2bfloat162_rn(x.x - f0.x, x.y - f0.y);
    __nv_bfloat162 l1 = __floats2bfloat162_rn(x.z - f1.x, x.w - f1.y);
    __nv_bfloat162 l2 = __floats2bfloat162_rn(y.x - f2.x, y.y - f2.y);
    __nv_bfloat162 l3 = __floats2bfloat162_rn(y.z - f3.x, y.w - f3.y);
    lo.x = *(uint32_t*)&l0; lo.y = *(uint32_t*)&l1;
    lo.z = *(uint32_t*)&l2; lo.w = *(uint32_t*)&l3;
}
__device__ __forceinline__ void cvt4(const float4 v, uint2& hi, uint2& lo) {
    __nv_bfloat162 h0 = __floats2bfloat162_rn(v.x, v.y);
    __nv_bfloat162 h1 = __floats2bfloat162_rn(v.z, v.w);
    hi.x = *(uint32_t*)&h0; hi.y = *(uint32_t*)&h1;
    float2 f0 = __bfloat1622float2(h0);
    float2 f1 = __bfloat1622float2(h1);
    __nv_bfloat162 l0 = __floats2bfloat162_rn(v.x - f0.x, v.y - f0.y);
    __nv_bfloat162 l1 = __floats2bfloat162_rn(v.z - f1.x, v.w - f1.y);
    lo.x = *(uint32_t*)&l0; lo.y = *(uint32_t*)&l1;
}

// ---------------------------------------------------------------------------
// Tiled transpose-convert X[KR,256] fp32 -> T_hi/lo [256,KR] bf16
// ---------------------------------------------------------------------------
__global__ void tconv_tiled(const float* __restrict__ X,
                            __nv_bfloat16* __restrict__ Th,
                            __nv_bfloat16* __restrict__ Tl, int KR) {
    __shared__ float tile[32][33];
    const int tx = threadIdx.x, ty = threadIdx.y;
    const int nbase = blockIdx.x * 32;
    const int kbase = blockIdx.y * 32;
    #pragma unroll
    for (int j = 0; j < 4; j++) {
        int r = ty + j * 8;
        tile[r][tx] = X[(size_t)(kbase + r) * DD + nbase + tx];
    }
    __syncthreads();
    #pragma unroll
    for (int j = 0; j < 4; j++) {
        int n = ty + j * 8;
        float v = tile[tx][n];
        __nv_bfloat16 h = __float2bfloat16(v);
        size_t o = (size_t)(nbase + n) * KR + kbase + tx;
        Th[o] = h;
        Tl[o] = __float2bfloat16(v - __bfloat162float(h));
    }
}

// ---------------------------------------------------------------------------
// Fused combine + transpose-convert (READ-ONLY P)
// ---------------------------------------------------------------------------
__global__ void combine_tconv(const float* __restrict__ Res,
                              const float* __restrict__ P,
                              const float* __restrict__ rs,
                              float* __restrict__ E1,
                              __nv_bfloat16* __restrict__ Th,
                              __nv_bfloat16* __restrict__ Tl) {
    __shared__ float tile[32][33];
    const int tx = threadIdx.x, ty = threadIdx.y;
    const int nbase = blockIdx.x * 32;
    const int kbase = blockIdx.y * 32;
    #pragma unroll
    for (int j = 0; j < 4; j++) {
        int r = ty + j * 8;
        size_t o = (size_t)(kbase + r) * DD + nbase + tx;
        float rinv = 1.0f / (rs[kbase + r] + 1.0f);
        float v = (Res[o] + P[o]) * rinv;
        E1[o] = v;
        tile[r][tx] = v;
    }
    __syncthreads();
    #pragma unroll
    for (int j = 0; j < 4; j++) {
        int n = ty + j * 8;
        float v = tile[tx][n];
        __nv_bfloat16 h = __float2bfloat16(v);
        size_t o = (size_t)(nbase + n) * NN + kbase + tx;
        Th[o] = h;
        Tl[o] = __float2bfloat16(v - __bfloat162float(h));
    }
}

// ---------------------------------------------------------------------------
// Persistent big GEMM v2 (R11, unchanged): CTA 128x128, 4 warps, BK=32, SW64.
// ---------------------------------------------------------------------------
#define TOTAL_CHUNKS2 32768
#define BUFB 32768
#define GEMM2_SMEM (1024 + 2 * BUFB)

__global__ __launch_bounds__(128, 2) void gemm_persist(
    const float* __restrict__ A,
    const __nv_bfloat16* __restrict__ Bth, const __nv_bfloat16* __restrict__ Btl,
    float* __restrict__ P, float* __restrict__ rs)
{
    extern __shared__ char sm[];
    uint32_t smb = smem_to_u32(sm);
    const int t = threadIdx.x;
    const int lane = t & 31;
    const int w = t >> 5;
    const int wm = (w >> 1) * 64;
    const int wn = (w & 1) * 64;
    const int ncta = gridDim.x;

    const int g0 = (int)(((long long)blockIdx.x * TOTAL_CHUNKS2) / ncta);
    const int g1 = (int)(((long long)(blockIdx.x + 1) * TOTAL_CHUNKS2) / ncta);

    const int aseg = t & 7;
    const int arow_b = (t >> 5) * 32 + ((t >> 3) & 3);

    const int a_r = lane & 15;
    const int a_c = (lane & 16) >> 1;
    const int b_r = (lane & 7) + ((lane >> 4) << 3);
    const int b_c = lane & 8;

    float acc[4][8][4];
    #pragma unroll
    for (int i = 0; i < 4; i++)
        #pragma unroll
        for (int j = 0; j < 8; j++)
            #pragma unroll
            for (int q = 0; q < 4; q++) acc[i][j][q] = 0.0f;
    float rsj[8];
    #pragma unroll
    for (int j = 0; j < 8; j++) rsj[j] = 0.0f;

    float4 aR[8];
    {
        int tile = g0 >> 8, kc = g0 & 255;
        int m0 = (tile >> 1) * 128, n0 = (tile & 1) * 128;
        #pragma unroll
        for (int j = 0; j < 8; j++)
            aR[j] = *(const float4*)(A + (size_t)(m0 + arow_b + j * 4) * NN + kc * 32 + aseg * 4);
        #pragma unroll
        for (int i = 0; i < 4; i++) {
            int idx = t + i * 128;
            int row = idx >> 2, seg = idx & 3;
            uint32_t so = SMEM_SWIZZLE_64B((uint32_t)(row * 64 + seg * 16));
            CP_ASYNC16(smb + 1024 + 16384 + so, Bth + (size_t)(n0 + row) * NN + kc * 32 + seg * 8);
            CP_ASYNC16(smb + 1024 + 24576 + so, Btl + (size_t)(n0 + row) * NN + kc * 32 + seg * 8);
        }
        CP_COMMIT();
    }

    for (int g = g0; g < g1; g++) {
        const int b = (g - g0) & 1;
        char* buf = sm + 1024 + b * BUFB;
        const uint32_t bufb = smb + 1024 + b * BUFB;
        const int tile = g >> 8;
        const int n0 = (tile & 1) * 128;
        const bool last_of_tile = (g + 1 == g1) || ((g + 1) >> 8 != tile);

        #pragma unroll
        for (int j = 0; j < 8; j++) {
            float4 v = aR[j];
            if (n0 == 0) rsj[j] += v.x + v.y + v.z + v.w;
            uint2 hi, lo;
            cvt4(v, hi, lo);
            uint32_t o = SMEM_SWIZZLE_64B((uint32_t)((arow_b + j * 4) * 64 + aseg * 8));
            *(uint2*)(buf + o)        = hi;
            *(uint2*)(buf + 8192 + o) = lo;
        }

        if (g + 1 < g1) {
            int tn = (g + 1) >> 8, kn = (g + 1) & 255;
            int m0n = (tn >> 1) * 128;
            const float* Ap2 = A + (size_t)(m0n + arow_b) * NN + kn * 32 + aseg * 4;
            #pragma unroll
            for (int j = 0; j < 8; j++)
                aR[j] = *(const float4*)(Ap2 + (size_t)j * 4 * NN);
        }

        CP_WAIT0();
        __syncthreads();

        if (g + 1 < g1) {
            int tn = (g + 1) >> 8, kn = (g + 1) & 255;
            int n0n = (tn & 1) * 128;
            uint32_t obuf = smb + 1024 + (b ^ 1) * BUFB;
            #pragma unroll
            for (int i = 0; i < 4; i++) {
                int idx = t + i * 128;
                int row = idx >> 2, seg = idx & 3;
                uint32_t so = SMEM_SWIZZLE_64B((uint32_t)(row * 64 + seg * 16));
                CP_ASYNC16(obuf + 16384 + so, Bth + (size_t)(n0n + row) * NN + kn * 32 + seg * 8);
                CP_ASYNC16(obuf + 24576 + so, Btl + (size_t)(n0n + row) * NN + kn * 32 + seg * 8);
            }
            CP_COMMIT();
        }

        {
            const uint32_t Ah = bufb;
            const uint32_t Al = bufb + 8192;
            const uint32_t Bh = bufb + 16384;
            const uint32_t Bl = bufb + 24576;
            #pragma unroll
            for (int ks = 0; ks < 2; ks++) {
                const int kb = ks * 16;
                uint32_t ah[4][4], al[4][4];
                #pragma unroll
                for (int mt = 0; mt < 4; mt++) {
                    uint32_t o = SMEM_SWIZZLE_64B(
                        (uint32_t)((wm + mt * 16 + a_r) * 64 + (kb + a_c) * 2));
                    ldsm4(ah[mt], Ah + o);
                    ldsm4(al[mt], Al + o);
                }
                #pragma unroll
                for (int g4 = 0; g4 < 4; g4++) {
                    uint32_t bh[4], bl[4];
                    uint32_t o = SMEM_SWIZZLE_64B(
                        (uint32_t)((wn + g4 * 16 + b_r) * 64 + (kb + b_c) * 2));
                    ldsm4(bh, Bh + o);
                    ldsm4(bl, Bl + o);
                    #pragma unroll
                    for (int mt = 0; mt < 4; mt++) {
                        mma16816(acc[mt][2 * g4],     ah[mt], bh[0], bh[1]);
                        mma16816(acc[mt][2 * g4 + 1], ah[mt], bh[2], bh[3]);
                        mma16816(acc[mt][2 * g4],     ah[mt], bl[0], bl[1]);
                        mma16816(acc[mt][2 * g4 + 1], ah[mt], bl[2], bl[3]);
                        mma16816(acc[mt][2 * g4],     al[mt], bh[0], bh[1]);
                        mma16816(acc[mt][2 * g4 + 1], al[mt], bh[2], bh[3]);
                    }
                }
            }
        }

        if (last_of_tile) {
            const int m0 = (tile >> 1) * 128;
            if (n0 == 0) {
                #pragma unroll
                for (int j = 0; j < 8; j++) {
                    float v = rsj[j];
                    v += __shfl_xor_sync(0xffffffffu, v, 1);
                    v += __shfl_xor_sync(0xffffffffu, v, 2);
                    v += __shfl_xor_sync(0xffffffffu, v, 4);
                    if ((t & 7) == 0) red_add_f32(rs + m0 + arow_b + j * 4, v);
                    rsj[j] = 0.0f;
                }
            }
            const int lq = lane >> 2;
            const int lr = lane & 3;
            #pragma unroll
            for (int mt = 0; mt < 4; mt++) {
                int rA = m0 + wm + mt * 16 + lq;
                #pragma unroll
                for (int nt = 0; nt < 8; nt++) {
                    int col = n0 + wn + nt * 8 + lr * 2;
                    float* a4 = acc[mt][nt];
                    red_add_v2(P + (size_t)rA * DD + col,       a4[0], a4[1]);
                    red_add_v2(P + (size_t)(rA + 8) * DD + col, a4[2], a4[3]);
                    a4[0] = a4[1] = a4[2] = a4[3] = 0.0f;
                }
            }
        }
    }
}

// ---------------------------------------------------------------------------
// Small tensor GEMM (GCN convs) with fused GCN-init epilogue and optional
// fused input combine: if Pin != nullptr, A := (A + Pin) / (rsin + 1) on load.
//   H    = A' @ X
//   Oini = dinv[row]^2 * H + bias
// ---------------------------------------------------------------------------
#define CH 64
#define BUF_BYTES 49152
#define GEMM_SMEM (1024 + 2 * BUF_BYTES)

__global__ __launch_bounds__(128, 2) void gemm_small(
    const float* __restrict__ A,
    const float* __restrict__ Pin, const float* __restrict__ rsin,
    const __nv_bfloat16* __restrict__ Bth, const __nv_bfloat16* __restrict__ Btl,
    float* __restrict__ Out,
    float* __restrict__ Oini,
    const float* __restrict__ dinv,
    const float* __restrict__ bias)
{
    constexpr int KT = DD;
    constexpr int NCH = KT / CH;
    extern __shared__ char sm[];
    uint32_t smb = smem_to_u32(sm);
    const int t = threadIdx.x;
    const int lane = t & 31;
    const int w = t >> 5;
    const int m0 = blockIdx.y * 64;
    const int n0 = blockIdx.x * 128;
    const int wn = w * 32;

    const int arow = t >> 1;
    const int koff = (t & 1) * 32;
    const size_t abase = (size_t)(m0 + arow) * KT + koff;
    const float* Ap = A + abase;
    const float* Pp = (Pin != nullptr) ? (Pin + abase) : nullptr;
    const float rinv = (Pin != nullptr) ? (1.0f / (rsin[m0 + arow] + 1.0f)) : 1.0f;
    const uint32_t roff = arow * 128 + koff * 2;

    const __nv_bfloat16* BhG = Bth + (size_t)n0 * KT;
    const __nv_bfloat16* BlG = Btl + (size_t)n0 * KT;

    const int a_r = lane & 15;
    const int a_c = (lane & 16) >> 1;
    const int b_r = (lane & 7) + ((lane >> 4) << 3);
    const int b_c = lane & 8;

    float acc[4][4][4];
    #pragma unroll
    for (int i = 0; i < 4; i++)
        #pragma unroll
        for (int j = 0; j < 4; j++)
            #pragma unroll
            for (int q = 0; q < 4; q++) acc[i][j][q] = 0.0f;

    float4 aR[8];
    #pragma unroll
    for (int j = 0; j < 8; j++) {
        float4 v = *(const float4*)(Ap + j * 4);
        if (Pin != nullptr) {
            float4 p = *(const float4*)(Pp + j * 4);
            v.x = (v.x + p.x) * rinv; v.y = (v.y + p.y) * rinv;
            v.z = (v.z + p.z) * rinv; v.w = (v.w + p.w) * rinv;
        }
        aR[j] = v;
    }

    #pragma unroll
    for (int i = 0; i < 8; i++) {
        int idx = t + i * 128;
        int row = idx >> 3, seg = idx & 7;
        uint32_t so = SMEM_SWIZZLE_128B((uint32_t)(row * 128 + seg * 16));
        CP_ASYNC16(smb + 1024 + 16384 + so, BhG + (size_t)row * KT + seg * 8);
        CP_ASYNC16(smb + 1024 + 32768 + so, BlG + (size_t)row * KT + seg * 8);
    }
    CP_COMMIT();

    for (int c = 0; c < NCH; c++) {
        const int b = c & 1;
        char* buf = sm + 1024 + b * BUF_BYTES;
        const uint32_t bufb = smb + 1024 + b * BUF_BYTES;

        #pragma unroll
        for (int j = 0; j < 4; j++) {
            uint4 hi, lo;
            cvt8(aR[2 * j], aR[2 * j + 1], hi, lo);
            uint32_t o = SMEM_SWIZZLE_128B(roff + j * 16);
            *(uint4*)(buf + o)        = hi;
            *(uint4*)(buf + 8192 + o) = lo;
        }
        if (c + 1 < NCH) {
            const float* Ap2 = Ap + (c + 1) * CH;
            const float* Pp2 = (Pin != nullptr) ? (Pp + (c + 1) * CH) : nullptr;
            #pragma unroll
            for (int j = 0; j < 8; j++) {
                float4 v = *(const float4*)(Ap2 + j * 4);
                if (Pin != nullptr) {
                    float4 p = *(const float4*)(Pp2 + j * 4);
                    v.x = (v.x + p.x) * rinv; v.y = (v.y + p.y) * rinv;
                    v.z = (v.z + p.z) * rinv; v.w = (v.w + p.w) * rinv;
                }
                aR[j] = v;
            }
        }
        CP_WAIT0();
        __syncthreads();
        if (c + 1 < NCH) {
            uint32_t obuf = smb + 1024 + (b ^ 1) * BUF_BYTES;
            const __nv_bfloat16* bh2 = BhG + (c + 1) * CH;
            const __nv_bfloat16* bl2 = BlG + (c + 1) * CH;
            #pragma unroll
            for (int i = 0; i < 8; i++) {
                int idx = t + i * 128;
                int row = idx >> 3, seg = idx & 7;
                uint32_t so = SMEM_SWIZZLE_128B((uint32_t)(row * 128 + seg * 16));
                CP_ASYNC16(obuf + 16384 + so, bh2 + (size_t)row * KT + seg * 8);
                CP_ASYNC16(obuf + 32768 + so, bl2 + (size_t)row * KT + seg * 8);
            }
            CP_COMMIT();
        }
        const uint32_t Ah = bufb;
        const uint32_t Al = bufb + 8192;
        const uint32_t Bh = bufb + 16384;
        const uint32_t Bl = bufb + 32768;
        #pragma unroll
        for (int ks = 0; ks < 4; ks++) {
            const int kb = ks * 16;
            uint32_t ah[4][4], al[4][4], bh[2][4], bl[2][4];
            #pragma unroll
            for (int mt = 0; mt < 4; mt++) {
                uint32_t o = SMEM_SWIZZLE_128B(
                    (uint32_t)((mt * 16 + a_r) * 128 + (kb + a_c) * 2));
                ldsm4(ah[mt], Ah + o);
                ldsm4(al[mt], Al + o);
            }
            #pragma unroll
            for (int p = 0; p < 2; p++) {
                uint32_t o = SMEM_SWIZZLE_128B(
                    (uint32_t)((wn + p * 16 + b_r) * 128 + (kb + b_c) * 2));
                ldsm4(bh[p], Bh + o);
                ldsm4(bl[p], Bl + o);
            }
            #pragma unroll
            for (int mt = 0; mt < 4; mt++) {
                #pragma unroll
                for (int nt = 0; nt < 4; nt++) {
                    uint32_t bh0 = bh[nt >> 1][(nt & 1) * 2];
                    uint32_t bh1 = bh[nt >> 1][(nt & 1) * 2 + 1];
                    uint32_t bl0 = bl[nt >> 1][(nt & 1) * 2];
                    uint32_t bl1 = bl[nt >> 1][(nt & 1) * 2 + 1];
                    mma16816(acc[mt][nt], ah[mt], bh0, bh1);
                    mma16816(acc[mt][nt], ah[mt], bl0, bl1);
                    mma16816(acc[mt][nt], al[mt], bh0, bh1);
                }
            }
        }
    }

    const int lq = lane >> 2;
    const int lr = lane & 3;
    #pragma unroll
    for (int mt = 0; mt < 4; mt++) {
        int rA = mt * 16 + lq;
        int rB = rA + 8;
        float dA = dinv[m0 + rA], dB = dinv[m0 + rB];
        float cA = dA * dA, cB = dB * dB;
        #pragma unroll
        for (int nt = 0; nt < 4; nt++) {
            int col = n0 + wn + nt * 8 + lr * 2;
            float* a4 = acc[mt][nt];
            float2 bv = *(const float2*)(bias + col);
            *(float2*)(Out + (size_t)(m0 + rA) * DD + col) = make_float2(a4[0], a4[1]);
            *(float2*)(Out + (size_t)(m0 + rB) * DD + col) = make_float2(a4[2], a4[3]);
            *(float2*)(Oini + (size_t)(m0 + rA) * DD + col) =
                make_float2(cA * a4[0] + bv.x, cA * a4[1] + bv.y);
            *(float2*)(Oini + (size_t)(m0 + rB) * DD + col) =
                make_float2(cB * a4[2] + bv.x, cB * a4[3] + bv.y);
        }
    }
}

// ---------------------------------------------------------------------------
// zero_P
// ---------------------------------------------------------------------------
__global__ void zero_P_kernel(float* __restrict__ P, float* __restrict__ rs) {
    int i = blockIdx.x * blockDim.x + threadIdx.x;
    ((float4*)P)[i] = make_float4(0.f, 0.f, 0.f, 0.f);
    if (i < NN) rs[i] = 0.0f;
}

// ---------------------------------------------------------------------------
// GCN degree chain (hoisted)
// ---------------------------------------------------------------------------
__global__ void init_deg_kernel(float* __restrict__ d1, float* __restrict__ d2) {
    int i = blockIdx.x * blockDim.x + threadIdx.x;
    if (i < NN) { d1[i] = 1.0f; d2[i] = 1.0f; }
}
__global__ void deg_acc_kernel(const int* __restrict__ dst, float* __restrict__ deg) {
    int e = blockIdx.x * blockDim.x + threadIdx.x;
    if (e < EE) atomicAdd(&deg[dst[e]], 1.0f);
}
__global__ void dinv2_kernel(float* __restrict__ d1, float* __restrict__ d2) {
    int i = blockIdx.x * blockDim.x + threadIdx.x;
    if (i < NN) { d1[i] = rsqrtf(d1[i]); d2[i] = rsqrtf(d2[i]); }
}

// ---------------------------------------------------------------------------
// Edge scatter: out[dst] += dinv[src]*dinv[dst]*h[src]
// ---------------------------------------------------------------------------
__global__ __launch_bounds__(256) void scatter_kernel(
    const int* __restrict__ src, const int* __restrict__ dst,
    const float* __restrict__ dinv,
    const float* __restrict__ h, float* __restrict__ out) {
    int warp = blockIdx.x * (blockDim.x >> 5) + (threadIdx.x >> 5);
    if (warp >= EE) return;
    int lane = threadIdx.x & 31;
    int s = src[warp];
    int d = dst[warp];
    float c = dinv[s] * dinv[d];
    const float4* hs = (const float4*)(h + (size_t)s * DD);
    float* od = out + (size_t)d * DD;
    float4 v0 = hs[lane];
    float4 v1 = hs[lane + 32];
    red_add_v4(od + lane * 4,        c * v0.x, c * v0.y, c * v0.z, c * v0.w);
    red_add_v4(od + (lane + 32) * 4, c * v1.x, c * v1.y, c * v1.z, c * v1.w);
}

// ---------------------------------------------------------------------------
extern "C" void kernel_launch(void* const* d_in, const int* in_sizes, int n_in,
                              void* d_out, int out_size)
{
    const float* emb   = (const float*)d_in[0];
    const float* Apath = (const float*)d_in[1];
    const int*   same  = (const int*)d_in[2];
    const int*   up    = (const int*)d_in[3];
    const float* Wsame = (const float*)d_in[4];
    const float* bsame = (const float*)d_in[5];
    const float* Wtop  = (const float*)d_in[6];
    const float* btop  = (const float*)d_in[7];
    float* out = (float*)d_out;

    float *gE1, *gH, *gO1, *gP, *gRS, *gD1, *gD2;
    __nv_bfloat16 *gBh, *gBl, *gWh, *gWl;
    cudaGetSymbolAddress((void**)&gE1, g_E1);
    cudaGetSymbolAddress((void**)&gH,  g_H);
    cudaGetSymbolAddress((void**)&gO1, g_O1);
    cudaGetSymbolAddress((void**)&gP,  g_P);
    cudaGetSymbolAddress((void**)&gRS, g_rs);
    cudaGetSymbolAddress((void**)&gD1, g_dinv1);
    cudaGetSymbolAddress((void**)&gD2, g_dinv2);
    cudaGetSymbolAddress((void**)&gBh, g_Bth);
    cudaGetSymbolAddress((void**)&gBl, g_Btl);
    cudaGetSymbolAddress((void**)&gWh, g_Wh);
    cudaGetSymbolAddress((void**)&gWl, g_Wl);

    cudaFuncSetAttribute(gemm_persist,
                         cudaFuncAttributeMaxDynamicSharedMemorySize, GEMM2_SMEM);
    cudaFuncSetAttribute(gemm_small,
                         cudaFuncAttributeMaxDynamicSharedMemorySize, GEMM_SMEM);

    int smCount = 148;
    cudaDeviceGetAttribute(&smCount, cudaDevAttrMultiProcessorCount, 0);
    int pgrid = 2 * smCount;

    dim3 smallGrid(2, 128);
    dim3 tcGrid(DD / 32, NN / 32);
    dim3 tcwGrid(DD / 32, DD / 32);
    dim3 tcBlk(32, 8);
    int ew = (NN * DD / 4) / 256;

    // ---- degree chains for both convs (depend only on edge indices)
    init_deg_kernel<<<NN / 256, 256>>>(gD1, gD2);
    deg_acc_kernel<<<EE / 256, 256>>>(same + EE, gD1);
    deg_acc_kernel<<<EE / 256, 256>>>(up + EE, gD2);
    dinv2_kernel<<<NN / 256, 256>>>(gD1, gD2);

    // ---- bottom_to_up level 0
    tconv_tiled<<<tcGrid, tcBlk>>>(emb, gBh, gBl, NN);
    zero_P_kernel<<<ew, 256>>>(gP, gRS);
    gemm_persist<<<pgrid, 128, GEMM2_SMEM>>>(Apath, gBh, gBl, gP, gRS);
    combine_tconv<<<tcGrid, tcBlk>>>(emb, gP, gRS, gE1, gBh, gBl);

    // ---- bottom_to_up level 1 (result consumed directly by conv1's GEMM)
    zero_P_kernel<<<ew, 256>>>(gP, gRS);
    gemm_persist<<<pgrid, 128, GEMM2_SMEM>>>(Apath + (size_t)NN * NN, gBh, gBl, gP, gRS);

    // ---- GCNConv 1 (same-level): A = (E1 + P)/(rs+1) fused; h=gH, agg in gO1
    tconv_tiled<<<tcwGrid, tcBlk>>>(Wsame, gWh, gWl, DD);
    gemm_small<<<smallGrid, 128, GEMM_SMEM>>>(gE1, gP, gRS, gWh, gWl, gH, gO1, gD1, bsame);
    scatter_kernel<<<EE / 8, 256>>>(same, same + EE, gD1, gH, gO1);

    // ---- GCNConv 2 (top-to-bottom): h=gH, aggregate in d_out
    tconv_tiled<<<tcwGrid, tcBlk>>>(Wtop, gWh, gWl, DD);
    gemm_small<<<smallGrid, 128, GEMM_SMEM>>>(gO1, nullptr, nullptr, gWh, gWl, gH, out, gD2, btop);
    scatter_kernel<<<EE / 8, 256>>>(up, up + EE, gD2, gH, out);
}

// round 16
// speedup vs baseline: 1.0031x; 1.0031x over previous
#include <cuda_runtime.h>
#include <cuda_bf16.h>
#include <cstdint>

#define NN 8192
#define DD 256
#define EE 131072

#define SMEM_SWIZZLE_128B(o) ((o) ^ (((o) >> 3) & 0x70))
#define SMEM_SWIZZLE_64B(o)  ((o) ^ (((o) >> 3) & 0x30))

// ---------------------------------------------------------------------------
// Scratch (static device allocations — allowed)
// ---------------------------------------------------------------------------
__device__ float g_E1[NN * DD];
__device__ float g_H[NN * DD];
__device__ float g_O1[NN * DD];
__device__ float g_P[NN * DD];
__device__ __nv_bfloat16 g_Bth[DD * NN];
__device__ __nv_bfloat16 g_Btl[DD * NN];
__device__ __nv_bfloat16 g_Wh[DD * DD];
__device__ __nv_bfloat16 g_Wl[DD * DD];
__device__ float g_rs[NN];
__device__ float g_dinv1[NN];
__device__ float g_dinv2[NN];

// ---------------------------------------------------------------------------
// PTX wrappers (sm_80/sm_90 base-target instructions only)
// ---------------------------------------------------------------------------
__device__ __forceinline__ uint32_t smem_to_u32(const void* p) {
    uint32_t a;
    asm("{ .reg .u64 t; cvta.to.shared.u64 t, %1; cvt.u32.u64 %0, t; }" : "=r"(a) : "l"(p));
    return a;
}
__device__ __forceinline__ void ldsm4(uint32_t* r, uint32_t addr) {
    asm volatile("ldmatrix.sync.aligned.m8n8.x4.shared.b16 {%0,%1,%2,%3}, [%4];"
                 : "=r"(r[0]), "=r"(r[1]), "=r"(r[2]), "=r"(r[3]) : "r"(addr));
}
__device__ __forceinline__ void mma16816(float* c, const uint32_t* a, uint32_t b0, uint32_t b1) {
    asm volatile(
        "mma.sync.aligned.m16n8k16.row.col.f32.bf16.bf16.f32 "
        "{%0,%1,%2,%3}, {%4,%5,%6,%7}, {%8,%9}, {%0,%1,%2,%3};"
        : "+f"(c[0]), "+f"(c[1]), "+f"(c[2]), "+f"(c[3])
        : "r"(a[0]), "r"(a[1]), "r"(a[2]), "r"(a[3]), "r"(b0), "r"(b1));
}
#define CP_ASYNC16(dst, src) \
    asm volatile("cp.async.cg.shared.global [%0], [%1], 16;" :: "r"(dst), "l"(src))
#define CP_COMMIT() asm volatile("cp.async.commit_group;" ::: "memory")
#define CP_WAIT0() asm volatile("cp.async.wait_group 0;" ::: "memory")
__device__ __forceinline__ void red_add_v4(float* p, float a, float b, float c, float d) {
    asm volatile("red.global.add.v4.f32 [%0], {%1, %2, %3, %4};"
                 :: "l"(p), "f"(a), "f"(b), "f"(c), "f"(d) : "memory");
}
__device__ __forceinline__ void red_add_v2(float* p, float a, float b) {
    asm volatile("red.global.add.v2.f32 [%0], {%1, %2};"
                 :: "l"(p), "f"(a), "f"(b) : "memory");
}
__device__ __forceinline__ void red_add_f32(float* p, float v) {
    asm volatile("red.global.add.f32 [%0], %1;" :: "l"(p), "f"(v) : "memory");
}

// ---------------------------------------------------------------------------
// conversions
// ---------------------------------------------------------------------------
__device__ __forceinline__ void cvt8(const float4 x, const float4 y, uint4& hi, uint4& lo) {
    __nv_bfloat162 h0 = __floats2bfloat162_rn(x.x, x.y);
    __nv_bfloat162 h1 = __floats2bfloat162_rn(x.z, x.w);
    __nv_bfloat162 h2 = __floats2bfloat162_rn(y.x, y.y);
    __nv_bfloat162 h3 = __floats2bfloat162_rn(y.z, y.w);
    hi.x = *(uint32_t*)&h0; hi.y = *(uint32_t*)&h1;
    hi.z = *(uint32_t*)&h2; hi.w = *(uint32_t*)&h3;
    float2 f0 = __bfloat1622float2(h0);
    float2 f1 = __bfloat1622float2(h1);
    float2 f2 = __bfloat1622float2(h2);
    float2 f3 = __bfloat1622float2(h3);
    __nv_bfloat162 l0 = __floats2bfloat162_rn(x.x - f0.x, x.y - f0.y);
    __nv_bfloat162 l1 = __floats2bfloat162_rn(x.z - f1.x, x.w - f1.y);
    __nv_bfloat162 l2 = __floats2bfloat162_rn(y.x - f2.x, y.y - f2.y);
    __nv_bfloat162 l3 = __floats2bfloat162_rn(y.z - f3.x, y.w - f3.y);
    lo.x = *(uint32_t*)&l0; lo.y = *(uint32_t*)&l1;
    lo.z = *(uint32_t*)&l2; lo.w = *(uint32_t*)&l3;
}
__device__ __forceinline__ void cvt4(const float4 v, uint2& hi, uint2& lo) {
    __nv_bfloat162 h0 = __floats2bfloat162_rn(v.x, v.y);
    __nv_bfloat162 h1 = __floats2bfloat162_rn(v.z, v.w);
    hi.x = *(uint32_t*)&h0; hi.y = *(uint32_t*)&h1;
    float2 f0 = __bfloat1622float2(h0);
    float2 f1 = __bfloat1622float2(h1);
    __nv_bfloat162 l0 = __floats2bfloat162_rn(v.x - f0.x, v.y - f0.y);
    __nv_bfloat162 l1 = __floats2bfloat162_rn(v.z - f1.x, v.w - f1.y);
    lo.x = *(uint32_t*)&l0; lo.y = *(uint32_t*)&l1;
}

// ---------------------------------------------------------------------------
// Tiled transpose-convert X[KR,256] fp32 -> T_hi/lo [256,KR] bf16
// ---------------------------------------------------------------------------
__global__ void tconv_tiled(const float* __restrict__ X,
                            __nv_bfloat16* __restrict__ Th,
                            __nv_bfloat16* __restrict__ Tl, int KR) {
    __shared__ float tile[32][33];
    const int tx = threadIdx.x, ty = threadIdx.y;
    const int nbase = blockIdx.x * 32;
    const int kbase = blockIdx.y * 32;
    #pragma unroll
    for (int j = 0; j < 4; j++) {
        int r = ty + j * 8;
        tile[r][tx] = X[(size_t)(kbase + r) * DD + nbase + tx];
    }
    __syncthreads();
    #pragma unroll
    for (int j = 0; j < 4; j++) {
        int n = ty + j * 8;
        float v = tile[tx][n];
        __nv_bfloat16 h = __float2bfloat16(v);
        size_t o = (size_t)(nbase + n) * KR + kbase + tx;
        Th[o] = h;
        Tl[o] = __float2bfloat16(v - __bfloat162float(h));
    }
}

// ---------------------------------------------------------------------------
// Fused combine + transpose-convert (READ-ONLY P)
// ---------------------------------------------------------------------------
__global__ void combine_tconv(const float* __restrict__ Res,
                              const float* __restrict__ P,
                              const float* __restrict__ rs,
                              float* __restrict__ E1,
                              __nv_bfloat16* __restrict__ Th,
                              __nv_bfloat16* __restrict__ Tl) {
    __shared__ float tile[32][33];
    const int tx = threadIdx.x, ty = threadIdx.y;
    const int nbase = blockIdx.x * 32;
    const int kbase = blockIdx.y * 32;
    #pragma unroll
    for (int j = 0; j < 4; j++) {
        int r = ty + j * 8;
        size_t o = (size_t)(kbase + r) * DD + nbase + tx;
        float rinv = 1.0f / (rs[kbase + r] + 1.0f);
        float v = (Res[o] + P[o]) * rinv;
        E1[o] = v;
        tile[r][tx] = v;
    }
    __syncthreads();
    #pragma unroll
    for (int j = 0; j < 4; j++) {
        int n = ty + j * 8;
        float v = tile[tx][n];
        __nv_bfloat16 h = __float2bfloat16(v);
        size_t o = (size_t)(nbase + n) * NN + kbase + tx;
        Th[o] = h;
        Tl[o] = __float2bfloat16(v - __bfloat162float(h));
    }
}

// ---------------------------------------------------------------------------
// Persistent big GEMM v2 (R11): CTA 128x128, 4 warps, BK=32, SW64.
// ---------------------------------------------------------------------------
#define TOTAL_CHUNKS2 32768
#define BUFB 32768
#define GEMM2_SMEM (1024 + 2 * BUFB)

__global__ __launch_bounds__(128, 2) void gemm_persist(
    const float* __restrict__ A,
    const __nv_bfloat16* __restrict__ Bth, const __nv_bfloat16* __restrict__ Btl,
    float* __restrict__ P, float* __restrict__ rs)
{
    extern __shared__ char sm[];
    uint32_t smb = smem_to_u32(sm);
    const int t = threadIdx.x;
    const int lane = t & 31;
    const int w = t >> 5;
    const int wm = (w >> 1) * 64;
    const int wn = (w & 1) * 64;
    const int ncta = gridDim.x;

    const int g0 = (int)(((long long)blockIdx.x * TOTAL_CHUNKS2) / ncta);
    const int g1 = (int)(((long long)(blockIdx.x + 1) * TOTAL_CHUNKS2) / ncta);

    const int aseg = t & 7;
    const int arow_b = (t >> 5) * 32 + ((t >> 3) & 3);

    const int a_r = lane & 15;
    const int a_c = (lane & 16) >> 1;
    const int b_r = (lane & 7) + ((lane >> 4) << 3);
    const int b_c = lane & 8;

    float acc[4][8][4];
    #pragma unroll
    for (int i = 0; i < 4; i++)
        #pragma unroll
        for (int j = 0; j < 8; j++)
            #pragma unroll
            for (int q = 0; q < 4; q++) acc[i][j][q] = 0.0f;
    float rsj[8];
    #pragma unroll
    for (int j = 0; j < 8; j++) rsj[j] = 0.0f;

    float4 aR[8];
    {
        int tile = g0 >> 8, kc = g0 & 255;
        int m0 = (tile >> 1) * 128, n0 = (tile & 1) * 128;
        #pragma unroll
        for (int j = 0; j < 8; j++)
            aR[j] = *(const float4*)(A + (size_t)(m0 + arow_b + j * 4) * NN + kc * 32 + aseg * 4);
        #pragma unroll
        for (int i = 0; i < 4; i++) {
            int idx = t + i * 128;
            int row = idx >> 2, seg = idx & 3;
            uint32_t so = SMEM_SWIZZLE_64B((uint32_t)(row * 64 + seg * 16));
            CP_ASYNC16(smb + 1024 + 16384 + so, Bth + (size_t)(n0 + row) * NN + kc * 32 + seg * 8);
            CP_ASYNC16(smb + 1024 + 24576 + so, Btl + (size_t)(n0 + row) * NN + kc * 32 + seg * 8);
        }
        CP_COMMIT();
    }

    for (int g = g0; g < g1; g++) {
        const int b = (g - g0) & 1;
        char* buf = sm + 1024 + b * BUFB;
        const uint32_t bufb = smb + 1024 + b * BUFB;
        const int tile = g >> 8;
        const int n0 = (tile & 1) * 128;
        const bool last_of_tile = (g + 1 == g1) || ((g + 1) >> 8 != tile);

        #pragma unroll
        for (int j = 0; j < 8; j++) {
            float4 v = aR[j];
            if (n0 == 0) rsj[j] += v.x + v.y + v.z + v.w;
            uint2 hi, lo;
            cvt4(v, hi, lo);
            uint32_t o = SMEM_SWIZZLE_64B((uint32_t)((arow_b + j * 4) * 64 + aseg * 8));
            *(uint2*)(buf + o)        = hi;
            *(uint2*)(buf + 8192 + o) = lo;
        }

        if (g + 1 < g1) {
            int tn = (g + 1) >> 8, kn = (g + 1) & 255;
            int m0n = (tn >> 1) * 128;
            const float* Ap2 = A + (size_t)(m0n + arow_b) * NN + kn * 32 + aseg * 4;
            #pragma unroll
            for (int j = 0; j < 8; j++)
                aR[j] = *(const float4*)(Ap2 + (size_t)j * 4 * NN);
        }

        CP_WAIT0();
        __syncthreads();

        if (g + 1 < g1) {
            int tn = (g + 1) >> 8, kn = (g + 1) & 255;
            int n0n = (tn & 1) * 128;
            uint32_t obuf = smb + 1024 + (b ^ 1) * BUFB;
            #pragma unroll
            for (int i = 0; i < 4; i++) {
                int idx = t + i * 128;
                int row = idx >> 2, seg = idx & 3;
                uint32_t so = SMEM_SWIZZLE_64B((uint32_t)(row * 64 + seg * 16));
                CP_ASYNC16(obuf + 16384 + so, Bth + (size_t)(n0n + row) * NN + kn * 32 + seg * 8);
                CP_ASYNC16(obuf + 24576 + so, Btl + (size_t)(n0n + row) * NN + kn * 32 + seg * 8);
            }
            CP_COMMIT();
        }

        {
            const uint32_t Ah = bufb;
            const uint32_t Al = bufb + 8192;
            const uint32_t Bh = bufb + 16384;
            const uint32_t Bl = bufb + 24576;
            #pragma unroll
            for (int ks = 0; ks < 2; ks++) {
                const int kb = ks * 16;
                uint32_t ah[4][4], al[4][4];
                #pragma unroll
                for (int mt = 0; mt < 4; mt++) {
                    uint32_t o = SMEM_SWIZZLE_64B(
                        (uint32_t)((wm + mt * 16 + a_r) * 64 + (kb + a_c) * 2));
                    ldsm4(ah[mt], Ah + o);
                    ldsm4(al[mt], Al + o);
                }
                #pragma unroll
                for (int g4 = 0; g4 < 4; g4++) {
                    uint32_t bh[4], bl[4];
                    uint32_t o = SMEM_SWIZZLE_64B(
                        (uint32_t)((wn + g4 * 16 + b_r) * 64 + (kb + b_c) * 2));
                    ldsm4(bh, Bh + o);
                    ldsm4(bl, Bl + o);
                    #pragma unroll
                    for (int mt = 0; mt < 4; mt++) {
                        mma16816(acc[mt][2 * g4],     ah[mt], bh[0], bh[1]);
                        mma16816(acc[mt][2 * g4 + 1], ah[mt], bh[2], bh[3]);
                        mma16816(acc[mt][2 * g4],     ah[mt], bl[0], bl[1]);
                        mma16816(acc[mt][2 * g4 + 1], ah[mt], bl[2], bl[3]);
                        mma16816(acc[mt][2 * g4],     al[mt], bh[0], bh[1]);
                        mma16816(acc[mt][2 * g4 + 1], al[mt], bh[2], bh[3]);
                    }
                }
            }
        }

        if (last_of_tile) {
            const int m0 = (tile >> 1) * 128;
            if (n0 == 0) {
                #pragma unroll
                for (int j = 0; j < 8; j++) {
                    float v = rsj[j];
                    v += __shfl_xor_sync(0xffffffffu, v, 1);
                    v += __shfl_xor_sync(0xffffffffu, v, 2);
                    v += __shfl_xor_sync(0xffffffffu, v, 4);
                    if ((t & 7) == 0) red_add_f32(rs + m0 + arow_b + j * 4, v);
                    rsj[j] = 0.0f;
                }
            }
            const int lq = lane >> 2;
            const int lr = lane & 3;
            #pragma unroll
            for (int mt = 0; mt < 4; mt++) {
                int rA = m0 + wm + mt * 16 + lq;
                #pragma unroll
                for (int nt = 0; nt < 8; nt++) {
                    int col = n0 + wn + nt * 8 + lr * 2;
                    float* a4 = acc[mt][nt];
                    red_add_v2(P + (size_t)rA * DD + col,       a4[0], a4[1]);
                    red_add_v2(P + (size_t)(rA + 8) * DD + col, a4[2], a4[3]);
                    a4[0] = a4[1] = a4[2] = a4[3] = 0.0f;
                }
            }
        }
    }
}

// ---------------------------------------------------------------------------
// Small tensor GEMM (GCN convs) with fused GCN-init epilogue:
//   H    = A @ X
//   Oini = dinv[row]^2 * H + bias
// ---------------------------------------------------------------------------
#define CH 64
#define BUF_BYTES 49152
#define GEMM_SMEM (1024 + 2 * BUF_BYTES)

__global__ __launch_bounds__(128, 2) void gemm_small(
    const float* __restrict__ A,
    const __nv_bfloat16* __restrict__ Bth, const __nv_bfloat16* __restrict__ Btl,
    float* __restrict__ Out,
    float* __restrict__ Oini,
    const float* __restrict__ dinv,
    const float* __restrict__ bias)
{
    constexpr int KT = DD;
    constexpr int NCH = KT / CH;
    extern __shared__ char sm[];
    uint32_t smb = smem_to_u32(sm);
    const int t = threadIdx.x;
    const int lane = t & 31;
    const int w = t >> 5;
    const int m0 = blockIdx.y * 64;
    const int n0 = blockIdx.x * 128;
    const int wn = w * 32;

    const int arow = t >> 1;
    const int koff = (t & 1) * 32;
    const float* Ap = A + (size_t)(m0 + arow) * KT + koff;
    const uint32_t roff = arow * 128 + koff * 2;

    const __nv_bfloat16* BhG = Bth + (size_t)n0 * KT;
    const __nv_bfloat16* BlG = Btl + (size_t)n0 * KT;

    const int a_r = lane & 15;
    const int a_c = (lane & 16) >> 1;
    const int b_r = (lane & 7) + ((lane >> 4) << 3);
    const int b_c = lane & 8;

    float acc[4][4][4];
    #pragma unroll
    for (int i = 0; i < 4; i++)
        #pragma unroll
        for (int j = 0; j < 4; j++)
            #pragma unroll
            for (int q = 0; q < 4; q++) acc[i][j][q] = 0.0f;

    float4 aR[8];
    #pragma unroll
    for (int j = 0; j < 8; j++) aR[j] = *(const float4*)(Ap + j * 4);

    #pragma unroll
    for (int i = 0; i < 8; i++) {
        int idx = t + i * 128;
        int row = idx >> 3, seg = idx & 7;
        uint32_t so = SMEM_SWIZZLE_128B((uint32_t)(row * 128 + seg * 16));
        CP_ASYNC16(smb + 1024 + 16384 + so, BhG + (size_t)row * KT + seg * 8);
        CP_ASYNC16(smb + 1024 + 32768 + so, BlG + (size_t)row * KT + seg * 8);
    }
    CP_COMMIT();

    for (int c = 0; c < NCH; c++) {
        const int b = c & 1;
        char* buf = sm + 1024 + b * BUF_BYTES;
        const uint32_t bufb = smb + 1024 + b * BUF_BYTES;

        #pragma unroll
        for (int j = 0; j < 4; j++) {
            uint4 hi, lo;
            cvt8(aR[2 * j], aR[2 * j + 1], hi, lo);
            uint32_t o = SMEM_SWIZZLE_128B(roff + j * 16);
            *(uint4*)(buf + o)        = hi;
            *(uint4*)(buf + 8192 + o) = lo;
        }
        if (c + 1 < NCH) {
            const float* Ap2 = Ap + (c + 1) * CH;
            #pragma unroll
            for (int j = 0; j < 8; j++) aR[j] = *(const float4*)(Ap2 + j * 4);
        }
        CP_WAIT0();
        __syncthreads();
        if (c + 1 < NCH) {
            uint32_t obuf = smb + 1024 + (b ^ 1) * BUF_BYTES;
            const __nv_bfloat16* bh2 = BhG + (c + 1) * CH;
            const __nv_bfloat16* bl2 = BlG + (c + 1) * CH;
            #pragma unroll
            for (int i = 0; i < 8; i++) {
                int idx = t + i * 128;
                int row = idx >> 3, seg = idx & 7;
                uint32_t so = SMEM_SWIZZLE_128B((uint32_t)(row * 128 + seg * 16));
                CP_ASYNC16(obuf + 16384 + so, bh2 + (size_t)row * KT + seg * 8);
                CP_ASYNC16(obuf + 32768 + so, bl2 + (size_t)row * KT + seg * 8);
            }
            CP_COMMIT();
        }
        const uint32_t Ah = bufb;
        const uint32_t Al = bufb + 8192;
        const uint32_t Bh = bufb + 16384;
        const uint32_t Bl = bufb + 32768;
        #pragma unroll
        for (int ks = 0; ks < 4; ks++) {
            const int kb = ks * 16;
            uint32_t ah[4][4], al[4][4], bh[2][4], bl[2][4];
            #pragma unroll
            for (int mt = 0; mt < 4; mt++) {
                uint32_t o = SMEM_SWIZZLE_128B(
                    (uint32_t)((mt * 16 + a_r) * 128 + (kb + a_c) * 2));
                ldsm4(ah[mt], Ah + o);
                ldsm4(al[mt], Al + o);
            }
            #pragma unroll
            for (int p = 0; p < 2; p++) {
                uint32_t o = SMEM_SWIZZLE_128B(
                    (uint32_t)((wn + p * 16 + b_r) * 128 + (kb + b_c) * 2));
                ldsm4(bh[p], Bh + o);
                ldsm4(bl[p], Bl + o);
            }
            #pragma unroll
            for (int mt = 0; mt < 4; mt++) {
                #pragma unroll
                for (int nt = 0; nt < 4; nt++) {
                    uint32_t bh0 = bh[nt >> 1][(nt & 1) * 2];
                    uint32_t bh1 = bh[nt >> 1][(nt & 1) * 2 + 1];
                    uint32_t bl0 = bl[nt >> 1][(nt & 1) * 2];
                    uint32_t bl1 = bl[nt >> 1][(nt & 1) * 2 + 1];
                    mma16816(acc[mt][nt], ah[mt], bh0, bh1);
                    mma16816(acc[mt][nt], ah[mt], bl0, bl1);
                    mma16816(acc[mt][nt], al[mt], bh0, bh1);
                }
            }
        }
    }

    const int lq = lane >> 2;
    const int lr = lane & 3;
    #pragma unroll
    for (int mt = 0; mt < 4; mt++) {
        int rA = mt * 16 + lq;
        int rB = rA + 8;
        float dA = dinv[m0 + rA], dB = dinv[m0 + rB];
        float cA = dA * dA, cB = dB * dB;
        #pragma unroll
        for (int nt = 0; nt < 4; nt++) {
            int col = n0 + wn + nt * 8 + lr * 2;
            float* a4 = acc[mt][nt];
            float2 bv = *(const float2*)(bias + col);
            *(float2*)(Out + (size_t)(m0 + rA) * DD + col) = make_float2(a4[0], a4[1]);
            *(float2*)(Out + (size_t)(m0 + rB) * DD + col) = make_float2(a4[2], a4[3]);
            *(float2*)(Oini + (size_t)(m0 + rA) * DD + col) =
                make_float2(cA * a4[0] + bv.x, cA * a4[1] + bv.y);
            *(float2*)(Oini + (size_t)(m0 + rB) * DD + col) =
                make_float2(cB * a4[2] + bv.x, cB * a4[3] + bv.y);
        }
    }
}

// ---------------------------------------------------------------------------
// combine (level 1, READ-ONLY P) / zero_P
// ---------------------------------------------------------------------------
__global__ void combine_kernel(const float* __restrict__ Res,
                               const float* __restrict__ P,
                               const float* __restrict__ rs,
                               float* __restrict__ O) {
    int i = blockIdx.x * blockDim.x + threadIdx.x;
    int row = i >> 6;
    float r = 1.0f / (rs[row] + 1.0f);
    float4 x = ((const float4*)Res)[i];
    float4 p = ((const float4*)P)[i];
    float4 o;
    o.x = (x.x + p.x) * r; o.y = (x.y + p.y) * r;
    o.z = (x.z + p.z) * r; o.w = (x.w + p.w) * r;
    ((float4*)O)[i] = o;
}

__global__ void zero_P_kernel(float* __restrict__ P, float* __restrict__ rs) {
    int i = blockIdx.x * blockDim.x + threadIdx.x;
    ((float4*)P)[i] = make_float4(0.f, 0.f, 0.f, 0.f);
    if (i < NN) rs[i] = 0.0f;
}

// ---------------------------------------------------------------------------
// GCN degree chain (hoisted; single merged accumulate over both edge lists)
// ---------------------------------------------------------------------------
__global__ void init_deg_kernel(float* __restrict__ d1, float* __restrict__ d2) {
    int i = blockIdx.x * blockDim.x + threadIdx.x;
    if (i < NN) { d1[i] = 1.0f; d2[i] = 1.0f; }
}
__global__ void deg_acc_both_kernel(const int* __restrict__ dst1,
                                    const int* __restrict__ dst2,
                                    float* __restrict__ d1,
                                    float* __restrict__ d2) {
    int e = blockIdx.x * blockDim.x + threadIdx.x;
    if (e < EE) atomicAdd(&d1[dst1[e]], 1.0f);
    else if (e < 2 * EE) atomicAdd(&d2[dst2[e - EE]], 1.0f);
}
__global__ void dinv2_kernel(float* __restrict__ d1, float* __restrict__ d2) {
    int i = blockIdx.x * blockDim.x + threadIdx.x;
    if (i < NN) { d1[i] = rsqrtf(d1[i]); d2[i] = rsqrtf(d2[i]); }
}

// ---------------------------------------------------------------------------
// Edge scatter: out[dst] += dinv[src]*dinv[dst]*h[src]
// ---------------------------------------------------------------------------
__global__ __launch_bounds__(256) void scatter_kernel(
    const int* __restrict__ src, const int* __restrict__ dst,
    const float* __restrict__ dinv,
    const float* __restrict__ h, float* __restrict__ out) {
    int warp = blockIdx.x * (blockDim.x >> 5) + (threadIdx.x >> 5);
    if (warp >= EE) return;
    int lane = threadIdx.x & 31;
    int s = src[warp];
    int d = dst[warp];
    float c = dinv[s] * dinv[d];
    const float4* hs = (const float4*)(h + (size_t)s * DD);
    float* od = out + (size_t)d * DD;
    float4 v0 = hs[lane];
    float4 v1 = hs[lane + 32];
    red_add_v4(od + lane * 4,        c * v0.x, c * v0.y, c * v0.z, c * v0.w);
    red_add_v4(od + (lane + 32) * 4, c * v1.x, c * v1.y, c * v1.z, c * v1.w);
}

// ---------------------------------------------------------------------------
extern "C" void kernel_launch(void* const* d_in, const int* in_sizes, int n_in,
                              void* d_out, int out_size)
{
    const float* emb   = (const float*)d_in[0];
    const float* Apath = (const float*)d_in[1];
    const int*   same  = (const int*)d_in[2];
    const int*   up    = (const int*)d_in[3];
    const float* Wsame = (const float*)d_in[4];
    const float* bsame = (const float*)d_in[5];
    const float* Wtop  = (const float*)d_in[6];
    const float* btop  = (const float*)d_in[7];
    float* out = (float*)d_out;

    float *gE1, *gH, *gO1, *gP, *gRS, *gD1, *gD2;
    __nv_bfloat16 *gBh, *gBl, *gWh, *gWl;
    cudaGetSymbolAddress((void**)&gE1, g_E1);
    cudaGetSymbolAddress((void**)&gH,  g_H);
    cudaGetSymbolAddress((void**)&gO1, g_O1);
    cudaGetSymbolAddress((void**)&gP,  g_P);
    cudaGetSymbolAddress((void**)&gRS, g_rs);
    cudaGetSymbolAddress((void**)&gD1, g_dinv1);
    cudaGetSymbolAddress((void**)&gD2, g_dinv2);
    cudaGetSymbolAddress((void**)&gBh, g_Bth);
    cudaGetSymbolAddress((void**)&gBl, g_Btl);
    cudaGetSymbolAddress((void**)&gWh, g_Wh);
    cudaGetSymbolAddress((void**)&gWl, g_Wl);

    cudaFuncSetAttribute(gemm_persist,
                         cudaFuncAttributeMaxDynamicSharedMemorySize, GEMM2_SMEM);
    cudaFuncSetAttribute(gemm_small,
                         cudaFuncAttributeMaxDynamicSharedMemorySize, GEMM_SMEM);

    int smCount = 148;
    cudaDeviceGetAttribute(&smCount, cudaDevAttrMultiProcessorCount, 0);
    int pgrid = 2 * smCount;

    dim3 smallGrid(2, 128);
    dim3 tcGrid(DD / 32, NN / 32);
    dim3 tcwGrid(DD / 32, DD / 32);
    dim3 tcBlk(32, 8);
    int ew = (NN * DD / 4) / 256;

    // ---- degree chains for both convs (depend only on edge indices)
    init_deg_kernel<<<NN / 256, 256>>>(gD1, gD2);
    deg_acc_both_kernel<<<(2 * EE) / 256, 256>>>(same + EE, up + EE, gD1, gD2);
    dinv2_kernel<<<NN / 256, 256>>>(gD1, gD2);

    // ---- bottom_to_up level 0
    tconv_tiled<<<tcGrid, tcBlk>>>(emb, gBh, gBl, NN);
    zero_P_kernel<<<ew, 256>>>(gP, gRS);
    gemm_persist<<<pgrid, 128, GEMM2_SMEM>>>(Apath, gBh, gBl, gP, gRS);
    combine_tconv<<<tcGrid, tcBlk>>>(emb, gP, gRS, gE1, gBh, gBl);

    // ---- bottom_to_up level 1
    zero_P_kernel<<<ew, 256>>>(gP, gRS);
    gemm_persist<<<pgrid, 128, GEMM2_SMEM>>>(Apath + (size_t)NN * NN, gBh, gBl, gP, gRS);
    combine_kernel<<<ew, 256>>>(gE1, gP, gRS, gE1);

    // ---- GCNConv 1 (same-level): h=gH, aggregate in gO1
    tconv_tiled<<<tcwGrid, tcBlk>>>(Wsame, gWh, gWl, DD);
    gemm_small<<<smallGrid, 128, GEMM_SMEM>>>(gE1, gWh, gWl, gH, gO1, gD1, bsame);
    scatter_kernel<<<EE / 8, 256>>>(same, same + EE, gD1, gH, gO1);

    // ---- GCNConv 2 (top-to-bottom): h=gH, aggregate in d_out
    tconv_tiled<<<tcwGrid, tcBlk>>>(Wtop, gWh, gWl, DD);
    gemm_small<<<smallGrid, 128, GEMM_SMEM>>>(gO1, gWh, gWl, gH, out, gD2, btop);
    scatter_kernel<<<EE / 8, 256>>>(up, up + EE, gD2, gH, out);
}

// round 17
// speedup vs baseline: 1.0089x; 1.0058x over previous
#include <cuda_runtime.h>
#include <cuda_bf16.h>
#include <cstdint>

#define NN 8192
#define DD 256
#define EE 131072

#define SMEM_SWIZZLE_128B(o) ((o) ^ (((o) >> 3) & 0x70))
#define SMEM_SWIZZLE_64B(o)  ((o) ^ (((o) >> 3) & 0x30))

// ---------------------------------------------------------------------------
// Scratch (static device allocations — allowed)
// ---------------------------------------------------------------------------
__device__ float g_E1[NN * DD];
__device__ float g_H[NN * DD];
__device__ float g_O1[NN * DD];
__device__ float g_P[NN * DD];
__device__ __nv_bfloat16 g_Bth[DD * NN];
__device__ __nv_bfloat16 g_Btl[DD * NN];
__device__ __nv_bfloat16 g_Wh[DD * DD];
__device__ __nv_bfloat16 g_Wl[DD * DD];
__device__ float g_rs[NN];
__device__ float g_deg1[NN];     // raw degree (incl. self-loop)
__device__ float g_deg2[NN];

// ---------------------------------------------------------------------------
// PTX wrappers (sm_80/sm_90 base-target instructions only)
// ---------------------------------------------------------------------------
__device__ __forceinline__ uint32_t smem_to_u32(const void* p) {
    uint32_t a;
    asm("{ .reg .u64 t; cvta.to.shared.u64 t, %1; cvt.u32.u64 %0, t; }" : "=r"(a) : "l"(p));
    return a;
}
__device__ __forceinline__ void ldsm4(uint32_t* r, uint32_t addr) {
    asm volatile("ldmatrix.sync.aligned.m8n8.x4.shared.b16 {%0,%1,%2,%3}, [%4];"
                 : "=r"(r[0]), "=r"(r[1]), "=r"(r[2]), "=r"(r[3]) : "r"(addr));
}
__device__ __forceinline__ void mma16816(float* c, const uint32_t* a, uint32_t b0, uint32_t b1) {
    asm volatile(
        "mma.sync.aligned.m16n8k16.row.col.f32.bf16.bf16.f32 "
        "{%0,%1,%2,%3}, {%4,%5,%6,%7}, {%8,%9}, {%0,%1,%2,%3};"
        : "+f"(c[0]), "+f"(c[1]), "+f"(c[2]), "+f"(c[3])
        : "r"(a[0]), "r"(a[1]), "r"(a[2]), "r"(a[3]), "r"(b0), "r"(b1));
}
#define CP_ASYNC16(dst, src) \
    asm volatile("cp.async.cg.shared.global [%0], [%1], 16;" :: "r"(dst), "l"(src))
#define CP_COMMIT() asm volatile("cp.async.commit_group;" ::: "memory")
#define CP_WAIT0() asm volatile("cp.async.wait_group 0;" ::: "memory")
__device__ __forceinline__ void red_add_v4(float* p, float a, float b, float c, float d) {
    asm volatile("red.global.add.v4.f32 [%0], {%1, %2, %3, %4};"
                 :: "l"(p), "f"(a), "f"(b), "f"(c), "f"(d) : "memory");
}
__device__ __forceinline__ void red_add_v2(float* p, float a, float b) {
    asm volatile("red.global.add.v2.f32 [%0], {%1, %2};"
                 :: "l"(p), "f"(a), "f"(b) : "memory");
}
__device__ __forceinline__ void red_add_f32(float* p, float v) {
    asm volatile("red.global.add.f32 [%0], %1;" :: "l"(p), "f"(v) : "memory");
}

// ---------------------------------------------------------------------------
// conversions
// ---------------------------------------------------------------------------
__device__ __forceinline__ void cvt8(const float4 x, const float4 y, uint4& hi, uint4& lo) {
    __nv_bfloat162 h0 = __floats2bfloat162_rn(x.x, x.y);
    __nv_bfloat162 h1 = __floats2bfloat162_rn(x.z, x.w);
    __nv_bfloat162 h2 = __floats2bfloat162_rn(y.x, y.y);
    __nv_bfloat162 h3 = __floats2bfloat162_rn(y.z, y.w);
    hi.x = *(uint32_t*)&h0; hi.y = *(uint32_t*)&h1;
    hi.z = *(uint32_t*)&h2; hi.w = *(uint32_t*)&h3;
    float2 f0 = __bfloat1622float2(h0);
    float2 f1 = __bfloat1622float2(h1);
    float2 f2 = __bfloat1622float2(h2);
    float2 f3 = __bfloat1622float2(h3);
    __nv_bfloat162 l0 = __floats2bfloat162_rn(x.x - f0.x, x.y - f0.y);
    __nv_bfloat162 l1 = __floats2bfloat162_rn(x.z - f1.x, x.w - f1.y);
    __nv_bfloat162 l2 = __floats2bfloat162_rn(y.x - f2.x, y.y - f2.y);
    __nv_bfloat162 l3 = __floats2bfloat162_rn(y.z - f3.x, y.w - f3.y);
    lo.x = *(uint32_t*)&l0; lo.y = *(uint32_t*)&l1;
    lo.z = *(uint32_t*)&l2; lo.w = *(uint32_t*)&l3;
}
__device__ __forceinline__ void cvt4(const float4 v, uint2& hi, uint2& lo) {
    __nv_bfloat162 h0 = __floats2bfloat162_rn(v.x, v.y);
    __nv_bfloat162 h1 = __floats2bfloat162_rn(v.z, v.w);
    hi.x = *(uint32_t*)&h0; hi.y = *(uint32_t*)&h1;
    float2 f0 = __bfloat1622float2(h0);
    float2 f1 = __bfloat1622float2(h1);
    __nv_bfloat162 l0 = __floats2bfloat162_rn(v.x - f0.x, v.y - f0.y);
    __nv_bfloat162 l1 = __floats2bfloat162_rn(v.z - f1.x, v.w - f1.y);
    lo.x = *(uint32_t*)&l0; lo.y = *(uint32_t*)&l1;
}

// ---------------------------------------------------------------------------
// Tiled transpose-convert X[KR,256] fp32 -> T_hi/lo [256,KR] bf16
// ---------------------------------------------------------------------------
__global__ void tconv_tiled(const float* __restrict__ X,
                            __nv_bfloat16* __restrict__ Th,
                            __nv_bfloat16* __restrict__ Tl, int KR) {
    __shared__ float tile[32][33];
    const int tx = threadIdx.x, ty = threadIdx.y;
    const int nbase = blockIdx.x * 32;
    const int kbase = blockIdx.y * 32;
    #pragma unroll
    for (int j = 0; j < 4; j++) {
        int r = ty + j * 8;
        tile[r][tx] = X[(size_t)(kbase + r) * DD + nbase + tx];
    }
    __syncthreads();
    #pragma unroll
    for (int j = 0; j < 4; j++) {
        int n = ty + j * 8;
        float v = tile[tx][n];
        __nv_bfloat16 h = __float2bfloat16(v);
        size_t o = (size_t)(nbase + n) * KR + kbase + tx;
        Th[o] = h;
        Tl[o] = __float2bfloat16(v - __bfloat162float(h));
    }
}

// ---------------------------------------------------------------------------
// Fused combine + transpose-convert (READ-ONLY P)
// ---------------------------------------------------------------------------
__global__ void combine_tconv(const float* __restrict__ Res,
                              const float* __restrict__ P,
                              const float* __restrict__ rs,
                              float* __restrict__ E1,
                              __nv_bfloat16* __restrict__ Th,
                              __nv_bfloat16* __restrict__ Tl) {
    __shared__ float tile[32][33];
    const int tx = threadIdx.x, ty = threadIdx.y;
    const int nbase = blockIdx.x * 32;
    const int kbase = blockIdx.y * 32;
    #pragma unroll
    for (int j = 0; j < 4; j++) {
        int r = ty + j * 8;
        size_t o = (size_t)(kbase + r) * DD + nbase + tx;
        float rinv = 1.0f / (rs[kbase + r] + 1.0f);
        float v = (Res[o] + P[o]) * rinv;
        E1[o] = v;
        tile[r][tx] = v;
    }
    __syncthreads();
    #pragma unroll
    for (int j = 0; j < 4; j++) {
        int n = ty + j * 8;
        float v = tile[tx][n];
        __nv_bfloat16 h = __float2bfloat16(v);
        size_t o = (size_t)(nbase + n) * NN + kbase + tx;
        Th[o] = h;
        Tl[o] = __float2bfloat16(v - __bfloat162float(h));
    }
}

// ---------------------------------------------------------------------------
// Persistent big GEMM v2 (R11): CTA 128x128, 4 warps, BK=32, SW64.
// ---------------------------------------------------------------------------
#define TOTAL_CHUNKS2 32768
#define BUFB 32768
#define GEMM2_SMEM (1024 + 2 * BUFB)

__global__ __launch_bounds__(128, 2) void gemm_persist(
    const float* __restrict__ A,
    const __nv_bfloat16* __restrict__ Bth, const __nv_bfloat16* __restrict__ Btl,
    float* __restrict__ P, float* __restrict__ rs)
{
    extern __shared__ char sm[];
    uint32_t smb = smem_to_u32(sm);
    const int t = threadIdx.x;
    const int lane = t & 31;
    const int w = t >> 5;
    const int wm = (w >> 1) * 64;
    const int wn = (w & 1) * 64;
    const int ncta = gridDim.x;

    const int g0 = (int)(((long long)blockIdx.x * TOTAL_CHUNKS2) / ncta);
    const int g1 = (int)(((long long)(blockIdx.x + 1) * TOTAL_CHUNKS2) / ncta);

    const int aseg = t & 7;
    const int arow_b = (t >> 5) * 32 + ((t >> 3) & 3);

    const int a_r = lane & 15;
    const int a_c = (lane & 16) >> 1;
    const int b_r = (lane & 7) + ((lane >> 4) << 3);
    const int b_c = lane & 8;

    float acc[4][8][4];
    #pragma unroll
    for (int i = 0; i < 4; i++)
        #pragma unroll
        for (int j = 0; j < 8; j++)
            #pragma unroll
            for (int q = 0; q < 4; q++) acc[i][j][q] = 0.0f;
    float rsj[8];
    #pragma unroll
    for (int j = 0; j < 8; j++) rsj[j] = 0.0f;

    float4 aR[8];
    {
        int tile = g0 >> 8, kc = g0 & 255;
        int m0 = (tile >> 1) * 128, n0 = (tile & 1) * 128;
        #pragma unroll
        for (int j = 0; j < 8; j++)
            aR[j] = *(const float4*)(A + (size_t)(m0 + arow_b + j * 4) * NN + kc * 32 + aseg * 4);
        #pragma unroll
        for (int i = 0; i < 4; i++) {
            int idx = t + i * 128;
            int row = idx >> 2, seg = idx & 3;
            uint32_t so = SMEM_SWIZZLE_64B((uint32_t)(row * 64 + seg * 16));
            CP_ASYNC16(smb + 1024 + 16384 + so, Bth + (size_t)(n0 + row) * NN + kc * 32 + seg * 8);
            CP_ASYNC16(smb + 1024 + 24576 + so, Btl + (size_t)(n0 + row) * NN + kc * 32 + seg * 8);
        }
        CP_COMMIT();
    }

    for (int g = g0; g < g1; g++) {
        const int b = (g - g0) & 1;
        char* buf = sm + 1024 + b * BUFB;
        const uint32_t bufb = smb + 1024 + b * BUFB;
        const int tile = g >> 8;
        const int n0 = (tile & 1) * 128;
        const bool last_of_tile = (g + 1 == g1) || ((g + 1) >> 8 != tile);

        #pragma unroll
        for (int j = 0; j < 8; j++) {
            float4 v = aR[j];
            if (n0 == 0) rsj[j] += v.x + v.y + v.z + v.w;
            uint2 hi, lo;
            cvt4(v, hi, lo);
            uint32_t o = SMEM_SWIZZLE_64B((uint32_t)((arow_b + j * 4) * 64 + aseg * 8));
            *(uint2*)(buf + o)        = hi;
            *(uint2*)(buf + 8192 + o) = lo;
        }

        if (g + 1 < g1) {
            int tn = (g + 1) >> 8, kn = (g + 1) & 255;
            int m0n = (tn >> 1) * 128;
            const float* Ap2 = A + (size_t)(m0n + arow_b) * NN + kn * 32 + aseg * 4;
            #pragma unroll
            for (int j = 0; j < 8; j++)
                aR[j] = *(const float4*)(Ap2 + (size_t)j * 4 * NN);
        }

        CP_WAIT0();
        __syncthreads();

        if (g + 1 < g1) {
            int tn = (g + 1) >> 8, kn = (g + 1) & 255;
            int n0n = (tn & 1) * 128;
            uint32_t obuf = smb + 1024 + (b ^ 1) * BUFB;
            #pragma unroll
            for (int i = 0; i < 4; i++) {
                int idx = t + i * 128;
                int row = idx >> 2, seg = idx & 3;
                uint32_t so = SMEM_SWIZZLE_64B((uint32_t)(row * 64 + seg * 16));
                CP_ASYNC16(obuf + 16384 + so, Bth + (size_t)(n0n + row) * NN + kn * 32 + seg * 8);
                CP_ASYNC16(obuf + 24576 + so, Btl + (size_t)(n0n + row) * NN + kn * 32 + seg * 8);
            }
            CP_COMMIT();
        }

        {
            const uint32_t Ah = bufb;
            const uint32_t Al = bufb + 8192;
            const uint32_t Bh = bufb + 16384;
            const uint32_t Bl = bufb + 24576;
            #pragma unroll
            for (int ks = 0; ks < 2; ks++) {
                const int kb = ks * 16;
                uint32_t ah[4][4], al[4][4];
                #pragma unroll
                for (int mt = 0; mt < 4; mt++) {
                    uint32_t o = SMEM_SWIZZLE_64B(
                        (uint32_t)((wm + mt * 16 + a_r) * 64 + (kb + a_c) * 2));
                    ldsm4(ah[mt], Ah + o);
                    ldsm4(al[mt], Al + o);
                }
                #pragma unroll
                for (int g4 = 0; g4 < 4; g4++) {
                    uint32_t bh[4], bl[4];
                    uint32_t o = SMEM_SWIZZLE_64B(
                        (uint32_t)((wn + g4 * 16 + b_r) * 64 + (kb + b_c) * 2));
                    ldsm4(bh, Bh + o);
                    ldsm4(bl, Bl + o);
                    #pragma unroll
                    for (int mt = 0; mt < 4; mt++) {
                        mma16816(acc[mt][2 * g4],     ah[mt], bh[0], bh[1]);
                        mma16816(acc[mt][2 * g4 + 1], ah[mt], bh[2], bh[3]);
                        mma16816(acc[mt][2 * g4],     ah[mt], bl[0], bl[1]);
                        mma16816(acc[mt][2 * g4 + 1], ah[mt], bl[2], bl[3]);
                        mma16816(acc[mt][2 * g4],     al[mt], bh[0], bh[1]);
                        mma16816(acc[mt][2 * g4 + 1], al[mt], bh[2], bh[3]);
                    }
                }
            }
        }

        if (last_of_tile) {
            const int m0 = (tile >> 1) * 128;
            if (n0 == 0) {
                #pragma unroll
                for (int j = 0; j < 8; j++) {
                    float v = rsj[j];
                    v += __shfl_xor_sync(0xffffffffu, v, 1);
                    v += __shfl_xor_sync(0xffffffffu, v, 2);
                    v += __shfl_xor_sync(0xffffffffu, v, 4);
                    if ((t & 7) == 0) red_add_f32(rs + m0 + arow_b + j * 4, v);
                    rsj[j] = 0.0f;
                }
            }
            const int lq = lane >> 2;
            const int lr = lane & 3;
            #pragma unroll
            for (int mt = 0; mt < 4; mt++) {
                int rA = m0 + wm + mt * 16 + lq;
                #pragma unroll
                for (int nt = 0; nt < 8; nt++) {
                    int col = n0 + wn + nt * 8 + lr * 2;
                    float* a4 = acc[mt][nt];
                    red_add_v2(P + (size_t)rA * DD + col,       a4[0], a4[1]);
                    red_add_v2(P + (size_t)(rA + 8) * DD + col, a4[2], a4[3]);
                    a4[0] = a4[1] = a4[2] = a4[3] = 0.0f;
                }
            }
        }
    }
}

// ---------------------------------------------------------------------------
// Small tensor GEMM (GCN convs) with fused GCN-init epilogue:
//   H    = A @ X
//   Oini = (1/deg[row]) * H + bias      (dinv^2 == 1/deg)
// ---------------------------------------------------------------------------
#define CH 64
#define BUF_BYTES 49152
#define GEMM_SMEM (1024 + 2 * BUF_BYTES)

__global__ __launch_bounds__(128, 2) void gemm_small(
    const float* __restrict__ A,
    const __nv_bfloat16* __restrict__ Bth, const __nv_bfloat16* __restrict__ Btl,
    float* __restrict__ Out,
    float* __restrict__ Oini,
    const float* __restrict__ deg,
    const float* __restrict__ bias)
{
    constexpr int KT = DD;
    constexpr int NCH = KT / CH;
    extern __shared__ char sm[];
    uint32_t smb = smem_to_u32(sm);
    const int t = threadIdx.x;
    const int lane = t & 31;
    const int w = t >> 5;
    const int m0 = blockIdx.y * 64;
    const int n0 = blockIdx.x * 128;
    const int wn = w * 32;

    const int arow = t >> 1;
    const int koff = (t & 1) * 32;
    const float* Ap = A + (size_t)(m0 + arow) * KT + koff;
    const uint32_t roff = arow * 128 + koff * 2;

    const __nv_bfloat16* BhG = Bth + (size_t)n0 * KT;
    const __nv_bfloat16* BlG = Btl + (size_t)n0 * KT;

    const int a_r = lane & 15;
    const int a_c = (lane & 16) >> 1;
    const int b_r = (lane & 7) + ((lane >> 4) << 3);
    const int b_c = lane & 8;

    float acc[4][4][4];
    #pragma unroll
    for (int i = 0; i < 4; i++)
        #pragma unroll
        for (int j = 0; j < 4; j++)
            #pragma unroll
            for (int q = 0; q < 4; q++) acc[i][j][q] = 0.0f;

    float4 aR[8];
    #pragma unroll
    for (int j = 0; j < 8; j++) aR[j] = *(const float4*)(Ap + j * 4);

    #pragma unroll
    for (int i = 0; i < 8; i++) {
        int idx = t + i * 128;
        int row = idx >> 3, seg = idx & 7;
        uint32_t so = SMEM_SWIZZLE_128B((uint32_t)(row * 128 + seg * 16));
        CP_ASYNC16(smb + 1024 + 16384 + so, BhG + (size_t)row * KT + seg * 8);
        CP_ASYNC16(smb + 1024 + 32768 + so, BlG + (size_t)row * KT + seg * 8);
    }
    CP_COMMIT();

    for (int c = 0; c < NCH; c++) {
        const int b = c & 1;
        char* buf = sm + 1024 + b * BUF_BYTES;
        const uint32_t bufb = smb + 1024 + b * BUF_BYTES;

        #pragma unroll
        for (int j = 0; j < 4; j++) {
            uint4 hi, lo;
            cvt8(aR[2 * j], aR[2 * j + 1], hi, lo);
            uint32_t o = SMEM_SWIZZLE_128B(roff + j * 16);
            *(uint4*)(buf + o)        = hi;
            *(uint4*)(buf + 8192 + o) = lo;
        }
        if (c + 1 < NCH) {
            const float* Ap2 = Ap + (c + 1) * CH;
            #pragma unroll
            for (int j = 0; j < 8; j++) aR[j] = *(const float4*)(Ap2 + j * 4);
        }
        CP_WAIT0();
        __syncthreads();
        if (c + 1 < NCH) {
            uint32_t obuf = smb + 1024 + (b ^ 1) * BUF_BYTES;
            const __nv_bfloat16* bh2 = BhG + (c + 1) * CH;
            const __nv_bfloat16* bl2 = BlG + (c + 1) * CH;
            #pragma unroll
            for (int i = 0; i < 8; i++) {
                int idx = t + i * 128;
                int row = idx >> 3, seg = idx & 7;
                uint32_t so = SMEM_SWIZZLE_128B((uint32_t)(row * 128 + seg * 16));
                CP_ASYNC16(obuf + 16384 + so, bh2 + (size_t)row * KT + seg * 8);
                CP_ASYNC16(obuf + 32768 + so, bl2 + (size_t)row * KT + seg * 8);
            }
            CP_COMMIT();
        }
        const uint32_t Ah = bufb;
        const uint32_t Al = bufb + 8192;
        const uint32_t Bh = bufb + 16384;
        const uint32_t Bl = bufb + 32768;
        #pragma unroll
        for (int ks = 0; ks < 4; ks++) {
            const int kb = ks * 16;
            uint32_t ah[4][4], al[4][4], bh[2][4], bl[2][4];
            #pragma unroll
            for (int mt = 0; mt < 4; mt++) {
                uint32_t o = SMEM_SWIZZLE_128B(
                    (uint32_t)((mt * 16 + a_r) * 128 + (kb + a_c) * 2));
                ldsm4(ah[mt], Ah + o);
                ldsm4(al[mt], Al + o);
            }
            #pragma unroll
            for (int p = 0; p < 2; p++) {
                uint32_t o = SMEM_SWIZZLE_128B(
                    (uint32_t)((wn + p * 16 + b_r) * 128 + (kb + b_c) * 2));
                ldsm4(bh[p], Bh + o);
                ldsm4(bl[p], Bl + o);
            }
            #pragma unroll
            for (int mt = 0; mt < 4; mt++) {
                #pragma unroll
                for (int nt = 0; nt < 4; nt++) {
                    uint32_t bh0 = bh[nt >> 1][(nt & 1) * 2];
                    uint32_t bh1 = bh[nt >> 1][(nt & 1) * 2 + 1];
                    uint32_t bl0 = bl[nt >> 1][(nt & 1) * 2];
                    uint32_t bl1 = bl[nt >> 1][(nt & 1) * 2 + 1];
                    mma16816(acc[mt][nt], ah[mt], bh0, bh1);
                    mma16816(acc[mt][nt], ah[mt], bl0, bl1);
                    mma16816(acc[mt][nt], al[mt], bh0, bh1);
                }
            }
        }
    }

    const int lq = lane >> 2;
    const int lr = lane & 3;
    #pragma unroll
    for (int mt = 0; mt < 4; mt++) {
        int rA = mt * 16 + lq;
        int rB = rA + 8;
        float cA = 1.0f / deg[m0 + rA];     // == dinv^2
        float cB = 1.0f / deg[m0 + rB];
        #pragma unroll
        for (int nt = 0; nt < 4; nt++) {
            int col = n0 + wn + nt * 8 + lr * 2;
            float* a4 = acc[mt][nt];
            float2 bv = *(const float2*)(bias + col);
            *(float2*)(Out + (size_t)(m0 + rA) * DD + col) = make_float2(a4[0], a4[1]);
            *(float2*)(Out + (size_t)(m0 + rB) * DD + col) = make_float2(a4[2], a4[3]);
            *(float2*)(Oini + (size_t)(m0 + rA) * DD + col) =
                make_float2(cA * a4[0] + bv.x, cA * a4[1] + bv.y);
            *(float2*)(Oini + (size_t)(m0 + rB) * DD + col) =
                make_float2(cB * a4[2] + bv.x, cB * a4[3] + bv.y);
        }
    }
}

// ---------------------------------------------------------------------------
// combine (level 1, READ-ONLY P)
// ---------------------------------------------------------------------------
__global__ void combine_kernel(const float* __restrict__ Res,
                               const float* __restrict__ P,
                               const float* __restrict__ rs,
                               float* __restrict__ O) {
    int i = blockIdx.x * blockDim.x + threadIdx.x;
    int row = i >> 6;
    float r = 1.0f / (rs[row] + 1.0f);
    float4 x = ((const float4*)Res)[i];
    float4 p = ((const float4*)P)[i];
    float4 o;
    o.x = (x.x + p.x) * r; o.y = (x.y + p.y) * r;
    o.z = (x.z + p.z) * r; o.w = (x.w + p.w) * r;
    ((float4*)O)[i] = o;
}

// zero P + rs; optionally also init deg arrays to 1 (first call only)
__global__ void zero_P_kernel(float* __restrict__ P, float* __restrict__ rs,
                              float* __restrict__ d1, float* __restrict__ d2) {
    int i = blockIdx.x * blockDim.x + threadIdx.x;
    ((float4*)P)[i] = make_float4(0.f, 0.f, 0.f, 0.f);
    if (i < NN) {
        rs[i] = 0.0f;
        if (d1 != nullptr) { d1[i] = 1.0f; d2[i] = 1.0f; }
    }
}

// ---------------------------------------------------------------------------
// Degree accumulate (both edge lists in one launch); raw degree kept
// ---------------------------------------------------------------------------
__global__ void deg_acc_both_kernel(const int* __restrict__ dst1,
                                    const int* __restrict__ dst2,
                                    float* __restrict__ d1,
                                    float* __restrict__ d2) {
    int e = blockIdx.x * blockDim.x + threadIdx.x;
    if (e < EE) atomicAdd(&d1[dst1[e]], 1.0f);
    else if (e < 2 * EE) atomicAdd(&d2[dst2[e - EE]], 1.0f);
}

// ---------------------------------------------------------------------------
// Edge scatter: out[dst] += h[src] / sqrt(deg[src]*deg[dst])
// ---------------------------------------------------------------------------
__global__ __launch_bounds__(256) void scatter_kernel(
    const int* __restrict__ src, const int* __restrict__ dst,
    const float* __restrict__ deg,
    const float* __restrict__ h, float* __restrict__ out) {
    int warp = blockIdx.x * (blockDim.x >> 5) + (threadIdx.x >> 5);
    if (warp >= EE) return;
    int lane = threadIdx.x & 31;
    int s = src[warp];
    int d = dst[warp];
    float c = rsqrtf(deg[s] * deg[d]);
    const float4* hs = (const float4*)(h + (size_t)s * DD);
    float* od = out + (size_t)d * DD;
    float4 v0 = hs[lane];
    float4 v1 = hs[lane + 32];
    red_add_v4(od + lane * 4,        c * v0.x, c * v0.y, c * v0.z, c * v0.w);
    red_add_v4(od + (lane + 32) * 4, c * v1.x, c * v1.y, c * v1.z, c * v1.w);
}

// ---------------------------------------------------------------------------
extern "C" void kernel_launch(void* const* d_in, const int* in_sizes, int n_in,
                              void* d_out, int out_size)
{
    const float* emb   = (const float*)d_in[0];
    const float* Apath = (const float*)d_in[1];
    const int*   same  = (const int*)d_in[2];
    const int*   up    = (const int*)d_in[3];
    const float* Wsame = (const float*)d_in[4];
    const float* bsame = (const float*)d_in[5];
    const float* Wtop  = (const float*)d_in[6];
    const float* btop  = (const float*)d_in[7];
    float* out = (float*)d_out;

    float *gE1, *gH, *gO1, *gP, *gRS, *gD1, *gD2;
    __nv_bfloat16 *gBh, *gBl, *gWh, *gWl;
    cudaGetSymbolAddress((void**)&gE1, g_E1);
    cudaGetSymbolAddress((void**)&gH,  g_H);
    cudaGetSymbolAddress((void**)&gO1, g_O1);
    cudaGetSymbolAddress((void**)&gP,  g_P);
    cudaGetSymbolAddress((void**)&gRS, g_rs);
    cudaGetSymbolAddress((void**)&gD1, g_deg1);
    cudaGetSymbolAddress((void**)&gD2, g_deg2);
    cudaGetSymbolAddress((void**)&gBh, g_Bth);
    cudaGetSymbolAddress((void**)&gBl, g_Btl);
    cudaGetSymbolAddress((void**)&gWh, g_Wh);
    cudaGetSymbolAddress((void**)&gWl, g_Wl);

    cudaFuncSetAttribute(gemm_persist,
                         cudaFuncAttributeMaxDynamicSharedMemorySize, GEMM2_SMEM);
    cudaFuncSetAttribute(gemm_small,
                         cudaFuncAttributeMaxDynamicSharedMemorySize, GEMM_SMEM);

    int smCount = 148;
    cudaDeviceGetAttribute(&smCount, cudaDevAttrMultiProcessorCount, 0);
    int pgrid = 2 * smCount;

    dim3 smallGrid(2, 128);
    dim3 tcGrid(DD / 32, NN / 32);
    dim3 tcwGrid(DD / 32, DD / 32);
    dim3 tcBlk(32, 8);
    int ew = (NN * DD / 4) / 256;

    // ---- level-0 prep: zero P/rs + init deg (fused), degree accumulate
    zero_P_kernel<<<ew, 256>>>(gP, gRS, gD1, gD2);
    deg_acc_both_kernel<<<(2 * EE) / 256, 256>>>(same + EE, up + EE, gD1, gD2);

    // ---- bottom_to_up level 0
    tconv_tiled<<<tcGrid, tcBlk>>>(emb, gBh, gBl, NN);
    gemm_persist<<<pgrid, 128, GEMM2_SMEM>>>(Apath, gBh, gBl, gP, gRS);
    combine_tconv<<<tcGrid, tcBlk>>>(emb, gP, gRS, gE1, gBh, gBl);

    // ---- bottom_to_up level 1
    zero_P_kernel<<<ew, 256>>>(gP, gRS, nullptr, nullptr);
    gemm_persist<<<pgrid, 128, GEMM2_SMEM>>>(Apath + (size_t)NN * NN, gBh, gBl, gP, gRS);
    combine_kernel<<<ew, 256>>>(gE1, gP, gRS, gE1);

    // ---- GCNConv 1 (same-level): h=gH, aggregate in gO1
    tconv_tiled<<<tcwGrid, tcBlk>>>(Wsame, gWh, gWl, DD);
    gemm_small<<<smallGrid, 128, GEMM_SMEM>>>(gE1, gWh, gWl, gH, gO1, gD1, bsame);
    scatter_kernel<<<EE / 8, 256>>>(same, same + EE, gD1, gH, gO1);

    // ---- GCNConv 2 (top-to-bottom): h=gH, aggregate in d_out
    tconv_tiled<<<tcwGrid, tcBlk>>>(Wtop, gWh, gWl, DD);
    gemm_small<<<smallGrid, 128, GEMM_SMEM>>>(gO1, gWh, gWl, gH, out, gD2, btop);
    scatter_kernel<<<EE / 8, 256>>>(up, up + EE, gD2, gH, out);
}